// round 6
// baseline (speedup 1.0000x reference)
#include <cuda_runtime.h>

#define PLANE  65536
#define TOT    262144

typedef unsigned long long ull;

__device__ __forceinline__ ull pk2(float x, float y) {
    ull r; asm("mov.b64 %0, {%1,%2};" : "=l"(r) : "f"(x), "f"(y)); return r;
}
__device__ __forceinline__ void upk2(ull v, float& x, float& y) {
    asm("mov.b64 {%0,%1}, %2;" : "=f"(x), "=f"(y) : "l"(v));
}
__device__ __forceinline__ ull ffma2(ull a, ull b, ull c) {
    ull d; asm("fma.rn.f32x2 %0, %1, %2, %3;" : "=l"(d) : "l"(a), "l"(b), "l"(c)); return d;
}
__device__ __forceinline__ unsigned f2t(float x) {
    unsigned u; asm("cvt.rna.tf32.f32 %0, %1;" : "=r"(u) : "f"(x)); return u;
}
__device__ __forceinline__ void mma8(float* d,
                                     unsigned a0, unsigned a1, unsigned a2, unsigned a3,
                                     unsigned b0, unsigned b1) {
    asm volatile("mma.sync.aligned.m16n8k8.row.col.f32.tf32.tf32.f32 "
                 "{%0,%1,%2,%3}, {%4,%5,%6,%7}, {%8,%9}, {%0,%1,%2,%3};"
                 : "+f"(d[0]), "+f"(d[1]), "+f"(d[2]), "+f"(d[3])
                 : "r"(a0), "r"(a1), "r"(a2), "r"(a3), "r"(b0), "r"(b1));
}

// ---------------- scratch -----------------------------------------------------
__device__ float g_QKV[1024 * 768];
__device__ float g_psum[16 * PLANE];
__device__ float g_merged[TOT];
__device__ float g_res1[TOT];
__device__ float g_res2[TOT];
__device__ float g_ffnh[1024 * 1024];
__device__ float g_pe2s[128 * 4];
__device__ float g_pe2bs[4];
__device__ float g_red[16];
__device__ unsigned g_count;
__device__ unsigned g_gen;

// ---------------- reset + fold pe2 (tiny kernel, runs before mega) -----------
__global__ void reset_k(const float* __restrict__ pe2w, const float* __restrict__ pe2b) {
    int tid = threadIdx.x;  // 128 threads
    if (tid == 0) { g_count = 0u; g_gen = 0u; }
    if (tid < 16) g_red[tid] = 0.f;
    #pragma unroll
    for (int h = 0; h < 4; h++) {
        float s = 0.f;
        #pragma unroll 8
        for (int c = 0; c < 64; c++) s += pe2w[tid * 256 + h * 64 + c];
        g_pe2s[tid * 4 + h] = s;
    }
    if (tid < 4) {
        float s = 0.f;
        for (int c = 0; c < 64; c++) s += pe2b[tid * 64 + c];
        g_pe2bs[tid] = s;
    }
}

// ---------------- device-wide barrier (all blocks resident) -------------------
__device__ __forceinline__ void gsync(unsigned nb, unsigned& lgen) {
    __syncthreads();
    lgen++;
    if (threadIdx.x == 0) {
        __threadfence();
        unsigned arr = atomicAdd(&g_count, 1u) + 1u;
        if (arr == nb * lgen) {
            atomicExch(&g_gen, lgen);
        } else {
            while (atomicAdd(&g_gen, 0u) < lgen) __nanosleep(64);
        }
        __threadfence();
    }
    __syncthreads();
}

// ---------------- smem overlays ------------------------------------------------
struct GemmS { unsigned As[2][32][72]; unsigned Bs[2][32][72]; float shr[2][8]; };
struct AttnS {
    union {
        struct { unsigned As[2][16][40]; unsigned Bs[2][16][264]; } s1;
        struct { unsigned Ps[32][264]; unsigned Vs[32][68]; } s2;
    } u;
    float srd[2][8][32];
};
struct PeS { float4 sW[128]; ull sS[128][4]; float sB[4]; };
#define SMEM_BYTES 45056
static_assert(sizeof(GemmS) <= SMEM_BYTES, "gemm smem");
static_assert(sizeof(AttnS) <= SMEM_BYTES, "attn smem");
static_assert(sizeof(PeS)   <= SMEM_BYTES, "pe smem");

// ---------------- TF32 GEMM tile: BM=64, BK=32, 256 threads -------------------
#define EPI_BIAS   0
#define EPI_BRELU  1
#define EPI_BRR    2
#define EPI_BRRLN  3

template<int BN, int MI, int NI, int WR, int EPI, int SRC3, int LNA>
__device__ void gemm_tile(char* sraw, int bx, int by,
    const float* __restrict__ A,
    const float* __restrict__ B0, const float* __restrict__ B1, const float* __restrict__ B2,
    const float* __restrict__ bias0, const float* __restrict__ bias1, const float* __restrict__ bias2,
    const float* __restrict__ R, float* __restrict__ C,
    const float* __restrict__ lnw, const float* __restrict__ lnb,
    int K, int lda, int ldb, int ldc)
{
    GemmS* S = (GemmS*)sraw;
    constexpr int BM = 64, BK = 32;
    constexpr int BPT = (BN * BK / 4) / 256;    // 2 for BN=64, 1 for BN=32
    int tid = threadIdx.x, w = tid >> 5, lane = tid & 31;
    int g = lane >> 2, t = lane & 3;
    int wr = w % WR, wc = w / WR;

    __syncthreads();  // smem reuse safety across tiles/phases

    const float* B = B0; const float* bias = bias0;
    int bcol0 = bx * BN;
    if (SRC3) {
        int sel = bx >> 2;
        B = (sel == 0) ? B0 : (sel == 1 ? B1 : B2);
        bias = (sel == 0) ? bias0 : (sel == 1 ? bias1 : bias2);
        bcol0 = (bx & 3) * BN;
    }
    const float* Ab = A + (long)(by * BM) * lda;
    const float* Bb = B + bcol0;
    int bat = (by * BM) >> 8;
    float lnm = 0.f, lnri = 0.f;
    if (LNA || EPI == EPI_BRRLN) {
        lnm = g_red[bat * 2] * (1.f / 65536.f);
        float var = g_red[bat * 2 + 1] * (1.f / 65536.f) - lnm * lnm;
        lnri = rsqrtf(var + 1e-5f);
    }

    // loader indices
    int aR[2], aC[2], bR[BPT], bC[BPT];
    #pragma unroll
    for (int i = 0; i < 2; i++) {
        int s = tid + i * 256;
        aR[i] = s >> 3; aC[i] = (s & 7) * 4;
    }
    #pragma unroll
    for (int i = 0; i < BPT; i++) {
        int s = tid + i * 256;
        bR[i] = s / (BN / 4); bC[i] = (s % (BN / 4)) * 4;
    }
    float4 rA[2], rB[BPT];

    auto ldg = [&](int kt) {
        int kb = kt * BK;
        #pragma unroll
        for (int i = 0; i < 2; i++) {
            float4 v = *(const float4*)(Ab + (long)aR[i] * lda + kb + aC[i]);
            if (LNA) {
                int p = ((by * BM + aR[i]) * lda + kb + aC[i]) & 65535;
                float4 wv = *(const float4*)(lnw + p);
                float4 bv = *(const float4*)(lnb + p);
                v.x = (v.x - lnm) * lnri * wv.x + bv.x;
                v.y = (v.y - lnm) * lnri * wv.y + bv.y;
                v.z = (v.z - lnm) * lnri * wv.z + bv.z;
                v.w = (v.w - lnm) * lnri * wv.w + bv.w;
            }
            rA[i] = v;
        }
        #pragma unroll
        for (int i = 0; i < BPT; i++)
            rB[i] = *(const float4*)(Bb + (long)(kb + bR[i]) * ldb + bC[i]);
    };
    auto sts = [&](int bf) {
        #pragma unroll
        for (int i = 0; i < 2; i++) {
            float4 v = rA[i];
            S->As[bf][aC[i] + 0][aR[i]] = f2t(v.x);
            S->As[bf][aC[i] + 1][aR[i]] = f2t(v.y);
            S->As[bf][aC[i] + 2][aR[i]] = f2t(v.z);
            S->As[bf][aC[i] + 3][aR[i]] = f2t(v.w);
        }
        #pragma unroll
        for (int i = 0; i < BPT; i++) {
            float4 v = rB[i];
            *(uint4*)&S->Bs[bf][bR[i]][bC[i]] =
                make_uint4(f2t(v.x), f2t(v.y), f2t(v.z), f2t(v.w));
        }
    };

    float acc[MI][NI][4] = {};
    int wm = wr * (MI * 16), wn = wc * (NI * 8);
    int KT = K / BK, buf = 0;

    ldg(0); sts(0); __syncthreads();
    for (int kt = 0; kt < KT; kt++) {
        if (kt + 1 < KT) ldg(kt + 1);
        #pragma unroll
        for (int ks = 0; ks < BK / 8; ks++) {
            unsigned af[MI][4], bfr[NI][2];
            #pragma unroll
            for (int mi = 0; mi < MI; mi++) {
                int m0 = wm + mi * 16 + g;
                af[mi][0] = S->As[buf][ks * 8 + t][m0];
                af[mi][1] = S->As[buf][ks * 8 + t][m0 + 8];
                af[mi][2] = S->As[buf][ks * 8 + t + 4][m0];
                af[mi][3] = S->As[buf][ks * 8 + t + 4][m0 + 8];
            }
            #pragma unroll
            for (int ni = 0; ni < NI; ni++) {
                int n0 = wn + ni * 8 + g;
                bfr[ni][0] = S->Bs[buf][ks * 8 + t][n0];
                bfr[ni][1] = S->Bs[buf][ks * 8 + t + 4][n0];
            }
            #pragma unroll
            for (int mi = 0; mi < MI; mi++)
                #pragma unroll
                for (int ni = 0; ni < NI; ni++)
                    mma8(acc[mi][ni], af[mi][0], af[mi][1], af[mi][2], af[mi][3],
                         bfr[ni][0], bfr[ni][1]);
        }
        if (kt + 1 < KT) { sts(buf ^ 1); __syncthreads(); buf ^= 1; }
    }

    int row0 = by * BM + wm;
    int ocol0 = bx * BN + wn;
    int bcolw = bcol0 + wn;
    float sum = 0.f, sq = 0.f;
    #pragma unroll
    for (int mi = 0; mi < MI; mi++)
        #pragma unroll
        for (int ni = 0; ni < NI; ni++)
            #pragma unroll
            for (int half = 0; half < 2; half++) {
                int r = row0 + mi * 16 + g + half * 8;
                int cl = ni * 8 + 2 * t;
                float x = acc[mi][ni][half * 2], y = acc[mi][ni][half * 2 + 1];
                float2 bv = *(const float2*)(bias + bcolw + cl);
                long idx = (long)r * ldc + ocol0 + cl;
                if (EPI == EPI_BIAS)  { x += bv.x; y += bv.y; }
                if (EPI == EPI_BRELU) { x = fmaxf(x + bv.x, 0.f); y = fmaxf(y + bv.y, 0.f); }
                if (EPI == EPI_BRR) {
                    float2 rv = *(const float2*)(R + idx);
                    x += bv.x + rv.x; y += bv.y + rv.y;
                    sum += x + y; sq += x * x + y * y;
                }
                if (EPI == EPI_BRRLN) {
                    float2 rv = *(const float2*)(R + idx);
                    int p = (int)(idx & 65535);
                    float2 wv = *(const float2*)(lnw + p);
                    float2 lv = *(const float2*)(lnb + p);
                    rv.x = (rv.x - lnm) * lnri * wv.x + lv.x;
                    rv.y = (rv.y - lnm) * lnri * wv.y + lv.y;
                    x += bv.x + rv.x; y += bv.y + rv.y;
                    sum += x + y; sq += x * x + y * y;
                }
                *(float2*)(C + idx) = make_float2(x, y);
            }
    if (EPI == EPI_BRR || EPI == EPI_BRRLN) {
        #pragma unroll
        for (int o = 16; o > 0; o >>= 1) {
            sum += __shfl_xor_sync(0xffffffffu, sum, o);
            sq  += __shfl_xor_sync(0xffffffffu, sq, o);
        }
        if (lane == 0) { S->shr[0][w] = sum; S->shr[1][w] = sq; }
        __syncthreads();
        if (tid == 0) {
            float ts = 0.f, tq = 0.f;
            #pragma unroll
            for (int i = 0; i < 8; i++) { ts += S->shr[0][i]; tq += S->shr[1][i]; }
            int off = (EPI == EPI_BRRLN) ? 8 : 0;
            atomicAdd(&g_red[off + bat * 2], ts);
            atomicAdd(&g_red[off + bat * 2 + 1], tq);
        }
    }
}

// ---------------- fused attention unit (256 threads) --------------------------
__device__ void attn_unit(char* sraw, int uidx,
                          const float* __restrict__ QKV,
                          const float* __restrict__ psum,
                          float* __restrict__ merged)
{
    AttnS* S = (AttnS*)sraw;
    int tid = threadIdx.x;
    int w = tid >> 5, lane = tid & 31, g = lane >> 2, t = lane & 3;
    int z = uidx >> 3, b = z >> 2, h = z & 3;
    int row0 = (uidx & 7) * 32;

    __syncthreads();  // smem reuse safety

    const float* Abase = QKV + (long)(b * 256 + row0) * 768 + 256 + h * 64;  // K rows
    const float* Bbase = QKV + (long)(b * 256) * 768 + h * 64;               // Q rows

    int aR = tid >> 2, aC = (tid & 3) * 4;
    int bR[4], bC[4];
    #pragma unroll
    for (int i = 0; i < 4; i++) { int s = tid + i * 256; bR[i] = s >> 2; bC[i] = (s & 3) * 4; }
    float4 ra; float4 rb[4];

    auto ldg1 = [&](int kc) {
        if (tid < 128) ra = *(const float4*)(Abase + (long)aR * 768 + kc * 16 + aC);
        #pragma unroll
        for (int i = 0; i < 4; i++)
            rb[i] = *(const float4*)(Bbase + (long)bR[i] * 768 + kc * 16 + bC[i]);
    };
    auto sts1 = [&](int bf) {
        if (tid < 128) {
            S->u.s1.As[bf][aC + 0][aR] = f2t(ra.x);
            S->u.s1.As[bf][aC + 1][aR] = f2t(ra.y);
            S->u.s1.As[bf][aC + 2][aR] = f2t(ra.z);
            S->u.s1.As[bf][aC + 3][aR] = f2t(ra.w);
        }
        #pragma unroll
        for (int i = 0; i < 4; i++) {
            S->u.s1.Bs[bf][bC[i] + 0][bR[i]] = f2t(rb[i].x);
            S->u.s1.Bs[bf][bC[i] + 1][bR[i]] = f2t(rb[i].y);
            S->u.s1.Bs[bf][bC[i] + 2][bR[i]] = f2t(rb[i].z);
            S->u.s1.Bs[bf][bC[i] + 3][bR[i]] = f2t(rb[i].w);
        }
    };

    float acc[2][4][4] = {};
    int buf = 0;
    ldg1(0); sts1(0); __syncthreads();
    #pragma unroll
    for (int kc = 0; kc < 4; kc++) {
        if (kc < 3) ldg1(kc + 1);
        #pragma unroll
        for (int ks = 0; ks < 2; ks++) {
            unsigned af[2][4];
            #pragma unroll
            for (int mi = 0; mi < 2; mi++) {
                int m0 = mi * 16 + g;
                af[mi][0] = S->u.s1.As[buf][ks * 8 + t][m0];
                af[mi][1] = S->u.s1.As[buf][ks * 8 + t][m0 + 8];
                af[mi][2] = S->u.s1.As[buf][ks * 8 + t + 4][m0];
                af[mi][3] = S->u.s1.As[buf][ks * 8 + t + 4][m0 + 8];
            }
            #pragma unroll
            for (int ni = 0; ni < 4; ni++) {
                int n0 = w * 32 + ni * 8 + g;
                unsigned b0 = S->u.s1.Bs[buf][ks * 8 + t][n0];
                unsigned b1 = S->u.s1.Bs[buf][ks * 8 + t + 4][n0];
                mma8(acc[0][ni], af[0][0], af[0][1], af[0][2], af[0][3], b0, b1);
                mma8(acc[1][ni], af[1][0], af[1][1], af[1][2], af[1][3], b0, b1);
            }
        }
        if (kc < 3) { sts1(buf ^ 1); __syncthreads(); buf ^= 1; }
    }

    // add psum, scale
    const float* pp = psum + (long)z * PLANE;
    #pragma unroll
    for (int mi = 0; mi < 2; mi++)
        #pragma unroll
        for (int ni = 0; ni < 4; ni++)
            #pragma unroll
            for (int half = 0; half < 2; half++) {
                int r = mi * 16 + g + half * 8;
                int c = w * 32 + ni * 8 + 2 * t;
                float2 pv = *(const float2*)(pp + (long)(row0 + r) * 256 + c);
                acc[mi][ni][half * 2]     = (acc[mi][ni][half * 2]     + pv.x) * 0.125f;
                acc[mi][ni][half * 2 + 1] = (acc[mi][ni][half * 2 + 1] + pv.y) * 0.125f;
            }

    // softmax over cols
    float fm[2][2];
    #pragma unroll
    for (int mi = 0; mi < 2; mi++)
        #pragma unroll
        for (int half = 0; half < 2; half++) {
            float m = -1e30f;
            #pragma unroll
            for (int ni = 0; ni < 4; ni++)
                m = fmaxf(m, fmaxf(acc[mi][ni][half * 2], acc[mi][ni][half * 2 + 1]));
            m = fmaxf(m, __shfl_xor_sync(0xffffffffu, m, 1));
            m = fmaxf(m, __shfl_xor_sync(0xffffffffu, m, 2));
            if (t == 0) S->srd[0][w][mi * 16 + g + half * 8] = m;
        }
    __syncthreads();
    #pragma unroll
    for (int mi = 0; mi < 2; mi++)
        #pragma unroll
        for (int half = 0; half < 2; half++) {
            int r = mi * 16 + g + half * 8;
            float m = S->srd[0][0][r];
            #pragma unroll
            for (int ww = 1; ww < 8; ww++) m = fmaxf(m, S->srd[0][ww][r]);
            fm[mi][half] = m;
        }
    #pragma unroll
    for (int mi = 0; mi < 2; mi++)
        #pragma unroll
        for (int half = 0; half < 2; half++) {
            float s = 0.f;
            #pragma unroll
            for (int ni = 0; ni < 4; ni++) {
                float v0 = __expf(acc[mi][ni][half * 2]     - fm[mi][half]);
                float v1 = __expf(acc[mi][ni][half * 2 + 1] - fm[mi][half]);
                acc[mi][ni][half * 2] = v0; acc[mi][ni][half * 2 + 1] = v1;
                s += v0 + v1;
            }
            s += __shfl_xor_sync(0xffffffffu, s, 1);
            s += __shfl_xor_sync(0xffffffffu, s, 2);
            if (t == 0) S->srd[1][w][mi * 16 + g + half * 8] = s;
        }
    __syncthreads();   // also retires stage-1 smem
    #pragma unroll
    for (int mi = 0; mi < 2; mi++)
        #pragma unroll
        for (int half = 0; half < 2; half++) {
            int r = mi * 16 + g + half * 8;
            float s = 0.f;
            #pragma unroll
            for (int ww = 0; ww < 8; ww++) s += S->srd[1][ww][r];
            float inv = 1.f / s;
            #pragma unroll
            for (int ni = 0; ni < 4; ni++) {
                int c = w * 32 + ni * 8 + 2 * t;
                S->u.s2.Ps[r][c]     = f2t(acc[mi][ni][half * 2] * inv);
                S->u.s2.Ps[r][c + 1] = f2t(acc[mi][ni][half * 2 + 1] * inv);
            }
        }

    // stage 2: O = P @ V (K=256 in 8 chunks of 32)
    float accO[2][4] = {};
    int wr2 = w & 1, wc2 = w >> 1;
    const float* Vb0 = QKV + (long)(b * 256) * 768 + 512 + h * 64;
    int vR = tid >> 4, vC = (tid & 15) * 4;
    #pragma unroll 1
    for (int c0 = 0; c0 < 8; c0++) {
        float4 v0 = *(const float4*)(Vb0 + (long)(c0 * 32 + vR) * 768 + vC);
        float4 v1 = *(const float4*)(Vb0 + (long)(c0 * 32 + vR + 16) * 768 + vC);
        __syncthreads();
        S->u.s2.Vs[vR][vC + 0] = f2t(v0.x); S->u.s2.Vs[vR][vC + 1] = f2t(v0.y);
        S->u.s2.Vs[vR][vC + 2] = f2t(v0.z); S->u.s2.Vs[vR][vC + 3] = f2t(v0.w);
        S->u.s2.Vs[vR + 16][vC + 0] = f2t(v1.x); S->u.s2.Vs[vR + 16][vC + 1] = f2t(v1.y);
        S->u.s2.Vs[vR + 16][vC + 2] = f2t(v1.z); S->u.s2.Vs[vR + 16][vC + 3] = f2t(v1.w);
        __syncthreads();
        #pragma unroll
        for (int ks = 0; ks < 4; ks++) {
            int kk = c0 * 32 + ks * 8;
            unsigned a0 = S->u.s2.Ps[wr2 * 16 + g][kk + t];
            unsigned a1 = S->u.s2.Ps[wr2 * 16 + g + 8][kk + t];
            unsigned a2 = S->u.s2.Ps[wr2 * 16 + g][kk + t + 4];
            unsigned a3 = S->u.s2.Ps[wr2 * 16 + g + 8][kk + t + 4];
            #pragma unroll
            for (int ni = 0; ni < 2; ni++) {
                int n0 = wc2 * 16 + ni * 8 + g;
                unsigned b0 = S->u.s2.Vs[ks * 8 + t][n0];
                unsigned b1 = S->u.s2.Vs[ks * 8 + t + 4][n0];
                mma8(accO[ni], a0, a1, a2, a3, b0, b1);
            }
        }
    }

    #pragma unroll
    for (int ni = 0; ni < 2; ni++)
        #pragma unroll
        for (int half = 0; half < 2; half++) {
            int r = row0 + wr2 * 16 + g + half * 8;
            int c = h * 64 + wc2 * 16 + ni * 8 + 2 * t;
            *(float2*)(merged + (long)(b * 256 + r) * 256 + c) =
                make_float2(accO[ni][half * 2], accO[ni][half * 2 + 1]);
        }
}

// ---------------- the megakernel ----------------------------------------------
__global__ void __launch_bounds__(256, 1) mega_k(
    const float* __restrict__ feat, const float* __restrict__ loc,
    const float* __restrict__ Kw,  const float* __restrict__ Kb,
    const float* __restrict__ Qw,  const float* __restrict__ Qb,
    const float* __restrict__ Vw,  const float* __restrict__ Vb,
    const float* __restrict__ Fw,  const float* __restrict__ Fb,
    const float* __restrict__ pe1w, const float* __restrict__ pe1b,
    const float* __restrict__ f1w, const float* __restrict__ f1b,
    const float* __restrict__ f2w, const float* __restrict__ f2b,
    const float* __restrict__ ln1w, const float* __restrict__ ln1b,
    const float* __restrict__ ln2w, const float* __restrict__ ln2b,
    float* __restrict__ out)
{
    extern __shared__ char sraw[];
    int tid = threadIdx.x;
    unsigned nb = gridDim.x;
    unsigned lgen = 0;

    // ---- P1: QKV GEMM (blocks [0,nQ)) + PE MLP (blocks [nQ,nb)) ----
    {
        int nQ = (int)(nb * 2u) / 5;
        if (nQ < 1) nQ = 1;
        if ((int)blockIdx.x < nQ) {
            for (int tt = blockIdx.x; tt < 192; tt += nQ)
                gemm_tile<64, 2, 2, 2, EPI_BIAS, 1, 0>(sraw, tt % 12, tt / 12,
                    feat, Qw, Kw, Vw, Qb, Kb, Vb, nullptr, g_QKV,
                    nullptr, nullptr, 256, 256, 256, 768);
        } else {
            PeS* P = (PeS*)sraw;
            if (tid < 128) {
                P->sW[tid] = make_float4(pe1b[tid], pe1w[tid], pe1w[128 + tid], pe1w[256 + tid]);
                float4 sv = *(const float4*)(g_pe2s + tid * 4);
                P->sS[tid][0] = pk2(sv.x, sv.x);
                P->sS[tid][1] = pk2(sv.y, sv.y);
                P->sS[tid][2] = pk2(sv.z, sv.z);
                P->sS[tid][3] = pk2(sv.w, sv.w);
            }
            if (tid < 4) P->sB[tid] = g_pe2bs[tid];
            __syncthreads();
            int npe = (int)nb - nQ;
            const float2* L = (const float2*)loc;
            float2* PS = (float2*)g_psum;
            for (int u = blockIdx.x - nQ; u < 512; u += npe) {
                int gid = u * 256 + tid;
                float2 l0 = L[3 * gid], l1 = L[3 * gid + 1], l2 = L[3 * gid + 2];
                ull A0 = pk2(P->sB[0], P->sB[0]), A1 = pk2(P->sB[1], P->sB[1]);
                ull A2 = pk2(P->sB[2], P->sB[2]), A3 = pk2(P->sB[3], P->sB[3]);
                #pragma unroll 4
                for (int i = 0; i < 128; i++) {
                    float4 wv = P->sW[i];
                    float h0 = fmaf(l1.x, wv.w, fmaf(l0.y, wv.z, fmaf(l0.x, wv.y, wv.x)));
                    float h1 = fmaf(l2.y, wv.w, fmaf(l2.x, wv.z, fmaf(l1.y, wv.y, wv.x)));
                    h0 = fmaxf(h0, 0.f); h1 = fmaxf(h1, 0.f);
                    ull hd = pk2(h0, h1);
                    A0 = ffma2(hd, P->sS[i][0], A0);
                    A1 = ffma2(hd, P->sS[i][1], A1);
                    A2 = ffma2(hd, P->sS[i][2], A2);
                    A3 = ffma2(hd, P->sS[i][3], A3);
                }
                int r0 = 2 * gid;
                int b = r0 >> 16, m = (r0 >> 8) & 255, k2 = (r0 & 255) >> 1;
                long base = ((long)b * 4) * 32768 + (long)m * 128 + k2;
                float x, y;
                upk2(A0, x, y); PS[base]             = make_float2(x, y);
                upk2(A1, x, y); PS[base + 32768]     = make_float2(x, y);
                upk2(A2, x, y); PS[base + 2 * 32768] = make_float2(x, y);
                upk2(A3, x, y); PS[base + 3 * 32768] = make_float2(x, y);
            }
        }
    }
    gsync(nb, lgen);

    // ---- P2: fused attention (128 units) ----
    for (int u = blockIdx.x; u < 128; u += nb)
        attn_unit(sraw, u, g_QKV, g_psum, g_merged);
    gsync(nb, lgen);

    // ---- P3: output projection + residual + LN1 stats (128 tiles) ----
    for (int tt = blockIdx.x; tt < 128; tt += nb)
        gemm_tile<32, 1, 2, 4, EPI_BRR, 0, 0>(sraw, tt % 8, tt / 8,
            g_merged, Fw, nullptr, nullptr, Fb, nullptr, nullptr, feat, g_res1,
            nullptr, nullptr, 256, 256, 256, 256);
    gsync(nb, lgen);

    // ---- P4: FFN1 with LN1 applied on A-load (256 tiles) ----
    for (int tt = blockIdx.x; tt < 256; tt += nb)
        gemm_tile<64, 2, 2, 2, EPI_BRELU, 0, 1>(sraw, tt % 16, tt / 16,
            g_res1, f1w, nullptr, nullptr, f1b, nullptr, nullptr, nullptr, g_ffnh,
            ln1w, ln1b, 256, 256, 1024, 1024);
    gsync(nb, lgen);

    // ---- P5: FFN2 + LN1(res1) residual + LN2 stats (128 tiles) ----
    for (int tt = blockIdx.x; tt < 128; tt += nb)
        gemm_tile<32, 1, 2, 4, EPI_BRRLN, 0, 0>(sraw, tt % 8, tt / 8,
            g_ffnh, f2w, nullptr, nullptr, f2b, nullptr, nullptr, g_res1, g_res2,
            ln1w, ln1b, 1024, 1024, 256, 256);
    gsync(nb, lgen);

    // ---- P6: LN2 apply -> out ----
    for (int gid = blockIdx.x * 256 + tid; gid < 65536; gid += nb * 256) {
        int bt = gid >> 14;
        float m   = g_red[8 + bt * 2] * (1.f / 65536.f);
        float var = g_red[8 + bt * 2 + 1] * (1.f / 65536.f) - m * m;
        float ri  = rsqrtf(var + 1e-5f);
        int p = gid & 16383;
        float4 x  = ((const float4*)g_res2)[gid];
        float4 wv = ((const float4*)ln2w)[p];
        float4 bv = ((const float4*)ln2b)[p];
        float4 o;
        o.x = (x.x - m) * ri * wv.x + bv.x;
        o.y = (x.y - m) * ri * wv.y + bv.y;
        o.z = (x.z - m) * ri * wv.z + bv.z;
        o.w = (x.w - m) * ri * wv.w + bv.w;
        ((float4*)out)[gid] = o;
    }
}

// ---------------- launch --------------------------------------------------------
extern "C" void kernel_launch(void* const* d_in, const int* in_sizes, int n_in,
                              void* d_out, int out_size) {
    const float* feat = (const float*)d_in[0];
    const float* loc  = (const float*)d_in[1];
    const float* Kw   = (const float*)d_in[2];
    const float* Kb   = (const float*)d_in[3];
    const float* Qw   = (const float*)d_in[4];
    const float* Qb   = (const float*)d_in[5];
    const float* Vw   = (const float*)d_in[6];
    const float* Vb   = (const float*)d_in[7];
    const float* Fw   = (const float*)d_in[8];
    const float* Fb   = (const float*)d_in[9];
    const float* pe1w = (const float*)d_in[10];
    const float* pe1b = (const float*)d_in[11];
    const float* pe2w = (const float*)d_in[12];
    const float* pe2b = (const float*)d_in[13];
    const float* f1w  = (const float*)d_in[14];
    const float* f1b  = (const float*)d_in[15];
    const float* f2w  = (const float*)d_in[16];
    const float* f2b  = (const float*)d_in[17];
    const float* ln1w = (const float*)d_in[18];
    const float* ln1b = (const float*)d_in[19];
    const float* ln2w = (const float*)d_in[20];
    const float* ln2b = (const float*)d_in[21];
    float* out = (float*)d_out;

    int dev = 0;
    cudaGetDevice(&dev);
    int nb = 0;
    cudaDeviceGetAttribute(&nb, cudaDevAttrMultiProcessorCount, dev);
    if (nb <= 0) nb = 128;

    reset_k<<<1, 128>>>(pe2w, pe2b);
    mega_k<<<nb, 256, SMEM_BYTES>>>(
        feat, loc, Kw, Kb, Qw, Qb, Vw, Vb, Fw, Fb,
        pe1w, pe1b, f1w, f1b, f2w, f2b, ln1w, ln1b, ln2w, ln2b, out);
}

// round 7
// speedup vs baseline: 1.1443x; 1.1443x over previous
#include <cuda_runtime.h>
#include <cuda_fp16.h>

#define PLANE  65536
#define TOT    262144

typedef unsigned long long ull;

__device__ __forceinline__ ull pk2(float x, float y) {
    ull r; asm("mov.b64 %0, {%1,%2};" : "=l"(r) : "f"(x), "f"(y)); return r;
}
__device__ __forceinline__ void upk2(ull v, float& x, float& y) {
    asm("mov.b64 {%0,%1}, %2;" : "=f"(x), "=f"(y) : "l"(v));
}
__device__ __forceinline__ ull ffma2(ull a, ull b, ull c) {
    ull d; asm("fma.rn.f32x2 %0, %1, %2, %3;" : "=l"(d) : "l"(a), "l"(b), "l"(c)); return d;
}
__device__ __forceinline__ unsigned f2t(float x) {
    unsigned u; asm("cvt.rna.tf32.f32 %0, %1;" : "=r"(u) : "f"(x)); return u;
}
__device__ __forceinline__ void mma8(float* d,
                                     unsigned a0, unsigned a1, unsigned a2, unsigned a3,
                                     unsigned b0, unsigned b1) {
    asm volatile("mma.sync.aligned.m16n8k8.row.col.f32.tf32.tf32.f32 "
                 "{%0,%1,%2,%3}, {%4,%5,%6,%7}, {%8,%9}, {%0,%1,%2,%3};"
                 : "+f"(d[0]), "+f"(d[1]), "+f"(d[2]), "+f"(d[3])
                 : "r"(a0), "r"(a1), "r"(a2), "r"(a3), "r"(b0), "r"(b1));
}

// typed vector load: 4 elements starting at element offset (fp32 or fp16 storage)
template<int H>
__device__ __forceinline__ float4 ldvec(const void* base, long elem) {
    if (H) {
        const __half* hp = (const __half*)base + elem;
        uint2 u = *(const uint2*)hp;
        __half2 h0 = *reinterpret_cast<__half2*>(&u.x);
        __half2 h1 = *reinterpret_cast<__half2*>(&u.y);
        float2 f0 = __half22float2(h0), f1 = __half22float2(h1);
        return make_float4(f0.x, f0.y, f1.x, f1.y);
    } else {
        return *(const float4*)((const float*)base + elem);
    }
}
template<int H>
__device__ __forceinline__ void st2v(void* base, long elem, float x, float y) {
    if (H) *(__half2*)((__half*)base + elem) = __floats2half2_rn(x, y);
    else   *(float2*)((float*)base + elem) = make_float2(x, y);
}

// ---------------- scratch ------------------------------------------------------
__device__ __half g_QKVh[1024 * 768];
__device__ __half g_psumh[16 * PLANE];
__device__ float  g_S[16 * PLANE];
__device__ __half g_Ph[16 * PLANE];
__device__ __half g_avph[2 * TOT];
__device__ float  g_part[4 * TOT];
__device__ float  g_res1[TOT];
__device__ float  g_res2[TOT];
__device__ __half g_ffnh[1024 * 1024];
__device__ float  g_pe2s[128 * 4];
__device__ float  g_pe2bs[4];
__device__ float  g_red[16];

// ---------------- prep: fold pe2, zero LN accumulators -------------------------
__global__ void prep_k(const float* __restrict__ pe2w, const float* __restrict__ pe2b) {
    int tid = threadIdx.x;  // 128 threads
    #pragma unroll
    for (int h = 0; h < 4; h++) {
        float s = 0.f;
        #pragma unroll 8
        for (int c = 0; c < 64; c++) s += pe2w[tid * 256 + h * 64 + c];
        g_pe2s[tid * 4 + h] = s;
    }
    if (tid < 4) {
        float s = 0.f;
        for (int c = 0; c < 64; c++) s += pe2b[tid * 64 + c];
        g_pe2bs[tid] = s;
    }
    if (tid < 16) g_red[tid] = 0.f;
}

// ---------------- PE MLP (folded), 2 rows/thread, f32x2, fp16 out --------------
__global__ void pe_k(const float* __restrict__ loc, const float* __restrict__ w1,
                     const float* __restrict__ b1) {
    __shared__ float4 sW[128];
    __shared__ ull    sS[128][4];
    __shared__ float  sB[4];
    int tid = threadIdx.x;
    if (tid < 128) {
        sW[tid] = make_float4(b1[tid], w1[tid], w1[128 + tid], w1[256 + tid]);
        float4 sv = *(const float4*)(g_pe2s + tid * 4);
        sS[tid][0] = pk2(sv.x, sv.x);
        sS[tid][1] = pk2(sv.y, sv.y);
        sS[tid][2] = pk2(sv.z, sv.z);
        sS[tid][3] = pk2(sv.w, sv.w);
    }
    if (tid < 4) sB[tid] = g_pe2bs[tid];
    __syncthreads();

    int gid = blockIdx.x * 256 + tid;       // < 131072, 2 rows each
    const float2* L = (const float2*)loc;
    float2 l0 = L[3 * gid], l1 = L[3 * gid + 1], l2 = L[3 * gid + 2];
    ull A0 = pk2(sB[0], sB[0]), A1 = pk2(sB[1], sB[1]);
    ull A2 = pk2(sB[2], sB[2]), A3 = pk2(sB[3], sB[3]);
    #pragma unroll 4
    for (int i = 0; i < 128; i++) {
        float4 w = sW[i];
        float h0 = fmaf(l1.x, w.w, fmaf(l0.y, w.z, fmaf(l0.x, w.y, w.x)));
        float h1 = fmaf(l2.y, w.w, fmaf(l2.x, w.z, fmaf(l1.y, w.y, w.x)));
        h0 = fmaxf(h0, 0.f); h1 = fmaxf(h1, 0.f);
        ull hd = pk2(h0, h1);
        A0 = ffma2(hd, sS[i][0], A0);
        A1 = ffma2(hd, sS[i][1], A1);
        A2 = ffma2(hd, sS[i][2], A2);
        A3 = ffma2(hd, sS[i][3], A3);
    }
    int r0 = 2 * gid;
    int b = r0 >> 16, m = (r0 >> 8) & 255, k2 = (r0 & 255) >> 1;
    __half2* P = (__half2*)g_psumh;
    long base = ((long)b * 4) * 32768 + (long)m * 128 + k2;
    float x, y;
    upk2(A0, x, y); P[base]             = __floats2half2_rn(x, y);
    upk2(A1, x, y); P[base + 32768]     = __floats2half2_rn(x, y);
    upk2(A2, x, y); P[base + 2 * 32768] = __floats2half2_rn(x, y);
    upk2(A3, x, y); P[base + 3 * 32768] = __floats2half2_rn(x, y);
}

// ---------------- TF32 GEMM: BM=BN=64, BK=32, 128 thr --------------------------
// TRB: B rows are [N][K] (dot along K). AH/BH/CH: half storage. LNA: apply LN1
// (stats g_red[0..7], params lnw/lnb) to A on load. SRC3: B/bias selected from
// 3 sources by blockIdx.x>>2 (QKV fusion). Split-K: sp = blockIdx.x / NBL.
#define EPI_NONE  0
#define EPI_BIAS  1
#define EPI_BRELU 2
#define EPI_SC    3

template<int TRB, int EPI, int ASUM, int NBL, int AH, int BH, int CH, int LNA, int SRC3>
__global__ void gtc(const void* __restrict__ A, const void* __restrict__ A2,
                    const void* __restrict__ Bp0, const void* __restrict__ Bp1,
                    const void* __restrict__ Bp2,
                    const float* __restrict__ bias0, const float* __restrict__ bias1,
                    const float* __restrict__ bias2,
                    const void* __restrict__ psum, void* __restrict__ C,
                    const float* __restrict__ lnw, const float* __restrict__ lnb,
                    int KSPL, int lda, int ldb, int ldc,
                    long sAb, long sAh, long sBb, long sBh, long sCb, long sCh,
                    long spC) {
    constexpr int BM = 64, BN = 64, BK = 32, NTHR = 128;
    constexpr int APT = 4, BPT = 4;
    __shared__ unsigned As[2][BK][72];
    __shared__ unsigned Bs[2][BK][72];

    int tid = threadIdx.x, w = tid >> 5, lane = tid & 31;
    int g = lane >> 2, t = lane & 3;
    int wr = w & 1, wc = w >> 1;
    int nb = blockIdx.x % NBL, sp = blockIdx.x / NBL;
    int z = blockIdx.z, zb = z >> 2, zh = z & 3;
    long kb0 = (long)sp * KSPL;

    const void* Bsel = Bp0;
    const float* bias = bias0;
    int bcol0;
    if (SRC3) {
        int sel = blockIdx.x >> 2;
        Bsel = (sel == 0) ? Bp0 : (sel == 1 ? Bp1 : Bp2);
        bias = (sel == 0) ? bias0 : (sel == 1 ? bias1 : bias2);
        bcol0 = (blockIdx.x & 3) * BN;
    } else {
        bcol0 = nb * BN;
    }

    long aBase = zb * sAb + zh * sAh + (long)(blockIdx.y * BM) * lda + kb0;
    long bBase;
    if (TRB) bBase = zb * sBb + zh * sBh + (long)(nb * BN) * ldb + kb0;
    else     bBase = zb * sBb + zh * sBh + kb0 * (long)ldb + bcol0;

    int bat = (blockIdx.y * BM) >> 8;
    float lnm = 0.f, lnri = 0.f;
    if (LNA) {
        lnm = g_red[bat * 2] * (1.f / 65536.f);
        float var = g_red[bat * 2 + 1] * (1.f / 65536.f) - lnm * lnm;
        lnri = rsqrtf(var + 1e-5f);
    }

    int aR[APT], aC[APT], bR[BPT], bC[BPT];
    #pragma unroll
    for (int i = 0; i < APT; i++) {
        int s = tid + i * NTHR;
        aR[i] = s >> 3; aC[i] = (s & 7) * 4;
    }
    #pragma unroll
    for (int i = 0; i < BPT; i++) {
        int s = tid + i * NTHR;
        if (TRB) { bR[i] = s >> 3; bC[i] = (s & 7) * 4; }
        else     { bR[i] = s >> 4; bC[i] = (s & 15) * 4; }
    }
    float4 rA[APT], rB[BPT];

    auto ldg = [&](int kt) {
        int kb = kt * BK;
        #pragma unroll
        for (int i = 0; i < APT; i++) {
            long off = aBase + (long)aR[i] * lda + kb + aC[i];
            float4 v = ldvec<AH>(A, off);
            if (ASUM) {
                float4 v2 = ldvec<AH>(A2, off);
                v.x += v2.x; v.y += v2.y; v.z += v2.z; v.w += v2.w;
            }
            if (LNA) {
                int p = (int)(((long)(blockIdx.y * BM + aR[i]) * lda + kb + aC[i]) & 65535);
                float4 wv = *(const float4*)(lnw + p);
                float4 bv = *(const float4*)(lnb + p);
                v.x = (v.x - lnm) * lnri * wv.x + bv.x;
                v.y = (v.y - lnm) * lnri * wv.y + bv.y;
                v.z = (v.z - lnm) * lnri * wv.z + bv.z;
                v.w = (v.w - lnm) * lnri * wv.w + bv.w;
            }
            rA[i] = v;
        }
        #pragma unroll
        for (int i = 0; i < BPT; i++) {
            long off;
            if (TRB) off = bBase + (long)bR[i] * ldb + kb + bC[i];
            else     off = bBase + (long)(kb + bR[i]) * ldb + bC[i];
            rB[i] = ldvec<BH>(Bsel, off);
        }
    };
    auto sts = [&](int bf) {
        #pragma unroll
        for (int i = 0; i < APT; i++) {
            float4 v = rA[i];
            As[bf][aC[i] + 0][aR[i]] = f2t(v.x);
            As[bf][aC[i] + 1][aR[i]] = f2t(v.y);
            As[bf][aC[i] + 2][aR[i]] = f2t(v.z);
            As[bf][aC[i] + 3][aR[i]] = f2t(v.w);
        }
        #pragma unroll
        for (int i = 0; i < BPT; i++) {
            float4 v = rB[i];
            if (TRB) {
                Bs[bf][bC[i] + 0][bR[i]] = f2t(v.x);
                Bs[bf][bC[i] + 1][bR[i]] = f2t(v.y);
                Bs[bf][bC[i] + 2][bR[i]] = f2t(v.z);
                Bs[bf][bC[i] + 3][bR[i]] = f2t(v.w);
            } else {
                *(uint4*)&Bs[bf][bR[i]][bC[i]] =
                    make_uint4(f2t(v.x), f2t(v.y), f2t(v.z), f2t(v.w));
            }
        }
    };

    float acc[2][4][4] = {};
    int wm = wr * 32, wn = wc * 32;
    int KT = KSPL / BK, buf = 0;

    ldg(0); sts(0); __syncthreads();
    for (int kt = 0; kt < KT; kt++) {
        if (kt + 1 < KT) ldg(kt + 1);
        #pragma unroll
        for (int ks = 0; ks < BK / 8; ks++) {
            unsigned af[2][4], bfr[4][2];
            #pragma unroll
            for (int mi = 0; mi < 2; mi++) {
                int m0 = wm + mi * 16 + g;
                af[mi][0] = As[buf][ks * 8 + t][m0];
                af[mi][1] = As[buf][ks * 8 + t][m0 + 8];
                af[mi][2] = As[buf][ks * 8 + t + 4][m0];
                af[mi][3] = As[buf][ks * 8 + t + 4][m0 + 8];
            }
            #pragma unroll
            for (int ni = 0; ni < 4; ni++) {
                int n0 = wn + ni * 8 + g;
                bfr[ni][0] = Bs[buf][ks * 8 + t][n0];
                bfr[ni][1] = Bs[buf][ks * 8 + t + 4][n0];
            }
            #pragma unroll
            for (int mi = 0; mi < 2; mi++)
                #pragma unroll
                for (int ni = 0; ni < 4; ni++)
                    mma8(acc[mi][ni], af[mi][0], af[mi][1], af[mi][2], af[mi][3],
                         bfr[ni][0], bfr[ni][1]);
        }
        if (kt + 1 < KT) { sts(buf ^ 1); __syncthreads(); buf ^= 1; }
    }

    long Cb = zb * sCb + zh * sCh + (long)sp * spC;
    int row0 = blockIdx.y * BM + wm;
    int ocol0 = (SRC3 ? blockIdx.x * BN : nb * BN) + wn;
    int bcolw = bcol0 + wn;
    #pragma unroll
    for (int mi = 0; mi < 2; mi++) {
        #pragma unroll
        for (int ni = 0; ni < 4; ni++) {
            int cl = ni * 8 + 2 * t;
            #pragma unroll
            for (int half = 0; half < 2; half++) {
                int r = row0 + mi * 16 + g + half * 8;
                float x = acc[mi][ni][half * 2], y = acc[mi][ni][half * 2 + 1];
                long idx = Cb + (long)r * ldc + ocol0 + cl;
                if (EPI == EPI_BIAS || EPI == EPI_BRELU) {
                    float2 bv = *(const float2*)(bias + bcolw + cl);
                    x += bv.x; y += bv.y;
                    if (EPI == EPI_BRELU) { x = fmaxf(x, 0.f); y = fmaxf(y, 0.f); }
                }
                if (EPI == EPI_SC) {
                    float2 pv = __half22float2(*(const __half2*)((const __half*)psum + idx));
                    x = (x + pv.x) * 0.125f; y = (y + pv.y) * 0.125f;
                }
                st2v<CH>(C, idx, x, y);
            }
        }
    }
}

// ---------------- softmax over last dim (256): fp32 in, fp16 out ---------------
__global__ void softmax_k(const float* __restrict__ S, __half* __restrict__ P) {
    int t = threadIdx.x, warp = t >> 5, lane = t & 31;
    long row = (long)blockIdx.x * 8 + warp;
    const float4* rp = (const float4*)(S + row * 256);
    float4 a = rp[lane];
    float4 b = rp[lane + 32];
    float mx = fmaxf(fmaxf(fmaxf(a.x, a.y), fmaxf(a.z, a.w)),
                     fmaxf(fmaxf(b.x, b.y), fmaxf(b.z, b.w)));
    #pragma unroll
    for (int o = 16; o > 0; o >>= 1) mx = fmaxf(mx, __shfl_xor_sync(0xffffffffu, mx, o));
    a.x = __expf(a.x - mx); a.y = __expf(a.y - mx); a.z = __expf(a.z - mx); a.w = __expf(a.w - mx);
    b.x = __expf(b.x - mx); b.y = __expf(b.y - mx); b.z = __expf(b.z - mx); b.w = __expf(b.w - mx);
    float sm = a.x + a.y + a.z + a.w + b.x + b.y + b.z + b.w;
    #pragma unroll
    for (int o = 16; o > 0; o >>= 1) sm += __shfl_xor_sync(0xffffffffu, sm, o);
    float inv = 1.f / sm;
    __half2* hp = (__half2*)(P + row * 256);
    hp[2 * lane]          = __floats2half2_rn(a.x * inv, a.y * inv);
    hp[2 * lane + 1]      = __floats2half2_rn(a.z * inv, a.w * inv);
    hp[64 + 2 * lane]     = __floats2half2_rn(b.x * inv, b.y * inv);
    hp[64 + 2 * lane + 1] = __floats2half2_rn(b.z * inv, b.w * inv);
}

// ---------------- split-K reduce + bias + residual (+LN on residual) + stats ---
// LNRES: residual R gets LN1 (stats g_red[0..7], params lnw/lnb) before add.
// Stats of output go to g_red[OFF..OFF+7].
template<int PPART, int LNRES, int OFF>
__global__ void redres_k(const float* __restrict__ parts, const float* __restrict__ bias,
                         const float* __restrict__ R, float* __restrict__ X,
                         const float* __restrict__ lnw, const float* __restrict__ lnb) {
    __shared__ float shr[2][8];
    int gid = blockIdx.x * 256 + threadIdx.x;       // float4 index < 65536
    int bt = gid >> 14;
    float lnm = 0.f, lnri = 0.f;
    if (LNRES) {
        lnm = g_red[bt * 2] * (1.f / 65536.f);
        float var = g_red[bt * 2 + 1] * (1.f / 65536.f) - lnm * lnm;
        lnri = rsqrtf(var + 1e-5f);
    }
    const float4* pp = (const float4*)parts;
    float4 a = pp[gid];
    #pragma unroll
    for (int p = 1; p < PPART; p++) {
        float4 v = pp[gid + p * (TOT / 4)];
        a.x += v.x; a.y += v.y; a.z += v.z; a.w += v.w;
    }
    float4 bv = ((const float4*)bias)[gid & 63];
    float4 rv = ((const float4*)R)[gid];
    if (LNRES) {
        int p = gid & 16383;
        float4 wv = ((const float4*)lnw)[p];
        float4 lv = ((const float4*)lnb)[p];
        rv.x = (rv.x - lnm) * lnri * wv.x + lv.x;
        rv.y = (rv.y - lnm) * lnri * wv.y + lv.y;
        rv.z = (rv.z - lnm) * lnri * wv.z + lv.z;
        rv.w = (rv.w - lnm) * lnri * wv.w + lv.w;
    }
    a.x += bv.x + rv.x; a.y += bv.y + rv.y; a.z += bv.z + rv.z; a.w += bv.w + rv.w;
    ((float4*)X)[gid] = a;
    float s = a.x + a.y + a.z + a.w;
    float q = a.x * a.x + a.y * a.y + a.z * a.z + a.w * a.w;
    #pragma unroll
    for (int o = 16; o > 0; o >>= 1) {
        s += __shfl_xor_sync(0xffffffffu, s, o);
        q += __shfl_xor_sync(0xffffffffu, q, o);
    }
    int lane = threadIdx.x & 31, wp = threadIdx.x >> 5;
    if (lane == 0) { shr[0][wp] = s; shr[1][wp] = q; }
    __syncthreads();
    if (threadIdx.x == 0) {
        float ts = 0.f, tq = 0.f;
        #pragma unroll
        for (int i = 0; i < 8; i++) { ts += shr[0][i]; tq += shr[1][i]; }
        atomicAdd(&g_red[OFF + bt * 2], ts);
        atomicAdd(&g_red[OFF + bt * 2 + 1], tq);
    }
}

// ---------------- LayerNorm apply (final) --------------------------------------
__global__ void ln_k(const float* __restrict__ X, const float* __restrict__ w,
                     const float* __restrict__ b, float* __restrict__ out) {
    int gid = blockIdx.x * blockDim.x + threadIdx.x;   // < 65536 float4s
    int bt = gid >> 14;
    float m   = g_red[8 + bt * 2] * (1.f / 65536.f);
    float var = g_red[8 + bt * 2 + 1] * (1.f / 65536.f) - m * m;
    float ri  = rsqrtf(var + 1e-5f);
    int p = gid & 16383;
    float4 x  = ((const float4*)X)[gid];
    float4 wv = ((const float4*)w)[p];
    float4 bv = ((const float4*)b)[p];
    float4 o;
    o.x = (x.x - m) * ri * wv.x + bv.x;
    o.y = (x.y - m) * ri * wv.y + bv.y;
    o.z = (x.z - m) * ri * wv.z + bv.z;
    o.w = (x.w - m) * ri * wv.w + bv.w;
    ((float4*)out)[gid] = o;
}

// ---------------- launch ---------------------------------------------------------
extern "C" void kernel_launch(void* const* d_in, const int* in_sizes, int n_in,
                              void* d_out, int out_size) {
    const float* feat = (const float*)d_in[0];
    const float* loc  = (const float*)d_in[1];
    const float* Kw   = (const float*)d_in[2];
    const float* Kb   = (const float*)d_in[3];
    const float* Qw   = (const float*)d_in[4];
    const float* Qb   = (const float*)d_in[5];
    const float* Vw   = (const float*)d_in[6];
    const float* Vb   = (const float*)d_in[7];
    const float* Fw   = (const float*)d_in[8];
    const float* Fb   = (const float*)d_in[9];
    const float* pe1w = (const float*)d_in[10];
    const float* pe1b = (const float*)d_in[11];
    const float* pe2w = (const float*)d_in[12];
    const float* pe2b = (const float*)d_in[13];
    const float* f1w  = (const float*)d_in[14];
    const float* f1b  = (const float*)d_in[15];
    const float* f2w  = (const float*)d_in[16];
    const float* f2b  = (const float*)d_in[17];
    const float* ln1w = (const float*)d_in[18];
    const float* ln1b = (const float*)d_in[19];
    const float* ln2w = (const float*)d_in[20];
    const float* ln2b = (const float*)d_in[21];
    float* out = (float*)d_out;

    __half *pQKV, *pPsum, *pPh, *pAvp, *pFfnh;
    float *pS, *pPart, *pRes1, *pRes2;
    cudaGetSymbolAddress((void**)&pQKV, g_QKVh);
    cudaGetSymbolAddress((void**)&pPsum, g_psumh);
    cudaGetSymbolAddress((void**)&pPh, g_Ph);
    cudaGetSymbolAddress((void**)&pAvp, g_avph);
    cudaGetSymbolAddress((void**)&pFfnh, g_ffnh);
    cudaGetSymbolAddress((void**)&pS, g_S);
    cudaGetSymbolAddress((void**)&pPart, g_part);
    cudaGetSymbolAddress((void**)&pRes1, g_res1);
    cudaGetSymbolAddress((void**)&pRes2, g_res2);

    prep_k<<<1, 128>>>(pe2w, pe2b);
    pe_k<<<512, 256>>>(loc, pe1w, pe1b);

    // QKV: [1024,256] @ {Qw|Kw|Vw} -> g_QKVh [1024,768] (half)
    gtc<0, EPI_BIAS, 0, 12, 0, 0, 1, 0, 1><<<dim3(12, 16, 1), 128>>>(
        feat, nullptr, Qw, Kw, Vw, Qb, Kb, Vb, nullptr, pQKV, nullptr, nullptr,
        256, 256, 256, 768, 0, 0, 0, 0, 0, 0, 0);

    // scores: per (b,h) K-rows · Q-rows^T + psum (half), *0.125 -> S fp32
    gtc<1, EPI_SC, 0, 4, 1, 1, 0, 0, 0><<<dim3(4, 4, 16), 128>>>(
        pQKV + 256, nullptr, pQKV, nullptr, nullptr, nullptr, nullptr, nullptr,
        pPsum, pS, nullptr, nullptr,
        64, 768, 768, 256, 196608, 64, 196608, 64, 262144, 65536, 0);

    softmax_k<<<512, 256>>>(pS, pPh);

    // merged partials = attn(half) @ V(half), split-K 2 -> avph (half)
    gtc<0, EPI_NONE, 0, 1, 1, 1, 1, 0, 0><<<dim3(2, 4, 16), 128>>>(
        pPh, nullptr, pQKV + 512, nullptr, nullptr, nullptr, nullptr, nullptr,
        nullptr, pAvp, nullptr, nullptr,
        128, 256, 768, 256, 262144, 65536, 196608, 64, 65536, 64, TOT);

    // output projection: A = avp0+avp1 (half), split-K 2 -> part fp32
    gtc<0, EPI_NONE, 1, 4, 1, 0, 0, 0, 0><<<dim3(8, 16, 1), 128>>>(
        pAvp, pAvp + TOT, Fw, nullptr, nullptr, nullptr, nullptr, nullptr,
        nullptr, pPart, nullptr, nullptr,
        128, 256, 256, 256, 0, 0, 0, 0, 0, 0, TOT);

    // reduce + Fb + feat residual -> res1, LN1 stats -> red[0..7]
    redres_k<2, 0, 0><<<256, 256>>>(pPart, Fb, feat, pRes1, nullptr, nullptr);

    // FFN1: A = LN1(res1) on load; bias+relu -> ffnh (half)
    gtc<0, EPI_BRELU, 0, 16, 0, 0, 1, 1, 0><<<dim3(16, 16, 1), 128>>>(
        pRes1, nullptr, f1w, nullptr, nullptr, f1b, nullptr, nullptr,
        nullptr, pFfnh, ln1w, ln1b,
        256, 256, 1024, 1024, 0, 0, 0, 0, 0, 0, 0);

    // FFN2: A = ffnh (half), split-K 4 -> part fp32
    gtc<0, EPI_NONE, 0, 4, 1, 0, 0, 0, 0><<<dim3(16, 16, 1), 128>>>(
        pFfnh, nullptr, f2w, nullptr, nullptr, nullptr, nullptr, nullptr,
        nullptr, pPart, nullptr, nullptr,
        256, 1024, 256, 256, 0, 0, 0, 0, 0, 0, TOT);

    // reduce + f2b + LN1(res1) residual -> res2, LN2 stats -> red[8..15]
    redres_k<4, 1, 8><<<256, 256>>>(pPart, f2b, pRes1, pRes2, ln1w, ln1b);

    // final LN2 -> out
    ln_k<<<256, 256>>>(pRes2, ln2w, ln2b, out);
}

// round 8
// speedup vs baseline: 1.2660x; 1.1064x over previous
#include <cuda_runtime.h>
#include <cuda_fp16.h>

#define PLANE  65536
#define TOT    262144

typedef unsigned long long ull;

__device__ __forceinline__ ull pk2(float x, float y) {
    ull r; asm("mov.b64 %0, {%1,%2};" : "=l"(r) : "f"(x), "f"(y)); return r;
}
__device__ __forceinline__ void upk2(ull v, float& x, float& y) {
    asm("mov.b64 {%0,%1}, %2;" : "=f"(x), "=f"(y) : "l"(v));
}
__device__ __forceinline__ ull ffma2(ull a, ull b, ull c) {
    ull d; asm("fma.rn.f32x2 %0, %1, %2, %3;" : "=l"(d) : "l"(a), "l"(b), "l"(c)); return d;
}
__device__ __forceinline__ unsigned f2t(float x) {
    unsigned u; asm("cvt.rna.tf32.f32 %0, %1;" : "=r"(u) : "f"(x)); return u;
}
__device__ __forceinline__ void mma8(float* d,
                                     unsigned a0, unsigned a1, unsigned a2, unsigned a3,
                                     unsigned b0, unsigned b1) {
    asm volatile("mma.sync.aligned.m16n8k8.row.col.f32.tf32.tf32.f32 "
                 "{%0,%1,%2,%3}, {%4,%5,%6,%7}, {%8,%9}, {%0,%1,%2,%3};"
                 : "+f"(d[0]), "+f"(d[1]), "+f"(d[2]), "+f"(d[3])
                 : "r"(a0), "r"(a1), "r"(a2), "r"(a3), "r"(b0), "r"(b1));
}

template<int H>
__device__ __forceinline__ float4 ldvec(const void* base, long elem) {
    if (H) {
        const __half* hp = (const __half*)base + elem;
        uint2 u = *(const uint2*)hp;
        __half2 h0 = *reinterpret_cast<__half2*>(&u.x);
        __half2 h1 = *reinterpret_cast<__half2*>(&u.y);
        float2 f0 = __half22float2(h0), f1 = __half22float2(h1);
        return make_float4(f0.x, f0.y, f1.x, f1.y);
    } else {
        return *(const float4*)((const float*)base + elem);
    }
}
template<int H>
__device__ __forceinline__ void st2v(void* base, long elem, float x, float y) {
    if (H) *(__half2*)((__half*)base + elem) = __floats2half2_rn(x, y);
    else   *(float2*)((float*)base + elem) = make_float2(x, y);
}

// ---------------- scratch ------------------------------------------------------
__device__ __half g_QKVh[1024 * 768];
__device__ __half g_psumh[16 * PLANE];
__device__ float  g_S[16 * PLANE];
__device__ __half g_Ph[16 * PLANE];
__device__ __half g_avph[2 * TOT];
__device__ float  g_part[4 * TOT];
__device__ float  g_res1[TOT];
__device__ float  g_res2[TOT];
__device__ __half g_ffnh[1024 * 1024];
__device__ float  g_pe2s[128 * 4];
__device__ float  g_pe2bs[4];
__device__ float  g_red[16];

// ---------------- prep: fold pe2, zero LN accumulators -------------------------
__global__ void prep_k(const float* __restrict__ pe2w, const float* __restrict__ pe2b) {
    int tid = threadIdx.x;  // 128 threads
    #pragma unroll
    for (int h = 0; h < 4; h++) {
        float s = 0.f;
        #pragma unroll 8
        for (int c = 0; c < 64; c++) s += pe2w[tid * 256 + h * 64 + c];
        g_pe2s[tid * 4 + h] = s;
    }
    if (tid < 4) {
        float s = 0.f;
        for (int c = 0; c < 64; c++) s += pe2b[tid * 64 + c];
        g_pe2bs[tid] = s;
    }
    if (tid < 16) g_red[tid] = 0.f;
}

// ---------------- PE MLP (folded), 2 rows/thread, f32x2, fp16 out --------------
__global__ void pe_k(const float* __restrict__ loc, const float* __restrict__ w1,
                     const float* __restrict__ b1) {
    __shared__ float4 sW[128];
    __shared__ ull    sS[128][4];
    __shared__ float  sB[4];
    int tid = threadIdx.x;
    if (tid < 128) {
        sW[tid] = make_float4(b1[tid], w1[tid], w1[128 + tid], w1[256 + tid]);
        float4 sv = *(const float4*)(g_pe2s + tid * 4);
        sS[tid][0] = pk2(sv.x, sv.x);
        sS[tid][1] = pk2(sv.y, sv.y);
        sS[tid][2] = pk2(sv.z, sv.z);
        sS[tid][3] = pk2(sv.w, sv.w);
    }
    if (tid < 4) sB[tid] = g_pe2bs[tid];
    __syncthreads();

    int gid = blockIdx.x * 256 + tid;       // < 131072, 2 rows each
    const float2* L = (const float2*)loc;
    float2 l0 = L[3 * gid], l1 = L[3 * gid + 1], l2 = L[3 * gid + 2];
    ull A0 = pk2(sB[0], sB[0]), A1 = pk2(sB[1], sB[1]);
    ull A2 = pk2(sB[2], sB[2]), A3 = pk2(sB[3], sB[3]);
    #pragma unroll 4
    for (int i = 0; i < 128; i++) {
        float4 w = sW[i];
        float h0 = fmaf(l1.x, w.w, fmaf(l0.y, w.z, fmaf(l0.x, w.y, w.x)));
        float h1 = fmaf(l2.y, w.w, fmaf(l2.x, w.z, fmaf(l1.y, w.y, w.x)));
        h0 = fmaxf(h0, 0.f); h1 = fmaxf(h1, 0.f);
        ull hd = pk2(h0, h1);
        A0 = ffma2(hd, sS[i][0], A0);
        A1 = ffma2(hd, sS[i][1], A1);
        A2 = ffma2(hd, sS[i][2], A2);
        A3 = ffma2(hd, sS[i][3], A3);
    }
    int r0 = 2 * gid;
    int b = r0 >> 16, m = (r0 >> 8) & 255, k2 = (r0 & 255) >> 1;
    __half2* P = (__half2*)g_psumh;
    long base = ((long)b * 4) * 32768 + (long)m * 128 + k2;
    float x, y;
    upk2(A0, x, y); P[base]             = __floats2half2_rn(x, y);
    upk2(A1, x, y); P[base + 32768]     = __floats2half2_rn(x, y);
    upk2(A2, x, y); P[base + 2 * 32768] = __floats2half2_rn(x, y);
    upk2(A3, x, y); P[base + 3 * 32768] = __floats2half2_rn(x, y);
}

// ---------------- TF32 GEMM: BM in {32,64}, BN=64, BK=32, 128 thr ---------------
#define EPI_NONE  0
#define EPI_BIAS  1
#define EPI_BRELU 2
#define EPI_SCL   3

template<int BM, int TRB, int EPI, int ASUM, int NBL, int AH, int BH, int CH, int LNA, int SRC3>
__global__ void gtc(const void* __restrict__ A, const void* __restrict__ A2,
                    const void* __restrict__ Bp0, const void* __restrict__ Bp1,
                    const void* __restrict__ Bp2,
                    const float* __restrict__ bias0, const float* __restrict__ bias1,
                    const float* __restrict__ bias2,
                    void* __restrict__ C,
                    const float* __restrict__ lnw, const float* __restrict__ lnb,
                    int KSPL, int lda, int ldb, int ldc,
                    long sAb, long sAh, long sBb, long sBh, long sCb, long sCh,
                    long spC) {
    constexpr int BN = 64, BK = 32, NTHR = 128;
    constexpr int MI = BM / 32;              // warp covers MI*16 rows
    constexpr int APT = BM / 16;
    constexpr int BPT = 4;
    __shared__ unsigned As[2][BK][BM + 8];
    __shared__ unsigned Bs[2][BK][72];

    int tid = threadIdx.x, w = tid >> 5, lane = tid & 31;
    int g = lane >> 2, t = lane & 3;
    int wr = w & 1, wc = w >> 1;
    int nb = blockIdx.x % NBL, sp = blockIdx.x / NBL;
    int z = blockIdx.z, zb = z >> 2, zh = z & 3;
    long kb0 = (long)sp * KSPL;

    const void* Bsel = Bp0;
    const float* bias = bias0;
    int bcol0;
    if (SRC3) {
        int sel = blockIdx.x >> 2;
        Bsel = (sel == 0) ? Bp0 : (sel == 1 ? Bp1 : Bp2);
        bias = (sel == 0) ? bias0 : (sel == 1 ? bias1 : bias2);
        bcol0 = (blockIdx.x & 3) * BN;
    } else {
        bcol0 = nb * BN;
    }

    long aBase = zb * sAb + zh * sAh + (long)(blockIdx.y * BM) * lda + kb0;
    long bBase;
    if (TRB) bBase = zb * sBb + zh * sBh + (long)(nb * BN) * ldb + kb0;
    else     bBase = zb * sBb + zh * sBh + kb0 * (long)ldb + bcol0;

    int bat = (blockIdx.y * BM) >> 8;
    float lnm = 0.f, lnri = 0.f;
    if (LNA) {
        lnm = g_red[bat * 2] * (1.f / 65536.f);
        float var = g_red[bat * 2 + 1] * (1.f / 65536.f) - lnm * lnm;
        lnri = rsqrtf(var + 1e-5f);
    }

    int aR[APT], aC[APT], bR[BPT], bC[BPT];
    #pragma unroll
    for (int i = 0; i < APT; i++) {
        int s = tid + i * NTHR;
        aR[i] = s >> 3; aC[i] = (s & 7) * 4;
    }
    #pragma unroll
    for (int i = 0; i < BPT; i++) {
        int s = tid + i * NTHR;
        if (TRB) { bR[i] = s >> 3; bC[i] = (s & 7) * 4; }
        else     { bR[i] = s >> 4; bC[i] = (s & 15) * 4; }
    }
    float4 rA[APT], rB[BPT];

    auto ldg = [&](int kt) {
        int kb = kt * BK;
        #pragma unroll
        for (int i = 0; i < APT; i++) {
            long off = aBase + (long)aR[i] * lda + kb + aC[i];
            float4 v = ldvec<AH>(A, off);
            if (ASUM) {
                float4 v2 = ldvec<AH>(A2, off);
                v.x += v2.x; v.y += v2.y; v.z += v2.z; v.w += v2.w;
            }
            if (LNA) {
                int p = (int)(((long)(blockIdx.y * BM + aR[i]) * lda + kb + aC[i]) & 65535);
                float4 wv = *(const float4*)(lnw + p);
                float4 bv = *(const float4*)(lnb + p);
                v.x = (v.x - lnm) * lnri * wv.x + bv.x;
                v.y = (v.y - lnm) * lnri * wv.y + bv.y;
                v.z = (v.z - lnm) * lnri * wv.z + bv.z;
                v.w = (v.w - lnm) * lnri * wv.w + bv.w;
            }
            rA[i] = v;
        }
        #pragma unroll
        for (int i = 0; i < BPT; i++) {
            long off;
            if (TRB) off = bBase + (long)bR[i] * ldb + kb + bC[i];
            else     off = bBase + (long)(kb + bR[i]) * ldb + bC[i];
            rB[i] = ldvec<BH>(Bsel, off);
        }
    };
    auto sts = [&](int bf) {
        #pragma unroll
        for (int i = 0; i < APT; i++) {
            float4 v = rA[i];
            As[bf][aC[i] + 0][aR[i]] = f2t(v.x);
            As[bf][aC[i] + 1][aR[i]] = f2t(v.y);
            As[bf][aC[i] + 2][aR[i]] = f2t(v.z);
            As[bf][aC[i] + 3][aR[i]] = f2t(v.w);
        }
        #pragma unroll
        for (int i = 0; i < BPT; i++) {
            float4 v = rB[i];
            if (TRB) {
                Bs[bf][bC[i] + 0][bR[i]] = f2t(v.x);
                Bs[bf][bC[i] + 1][bR[i]] = f2t(v.y);
                Bs[bf][bC[i] + 2][bR[i]] = f2t(v.z);
                Bs[bf][bC[i] + 3][bR[i]] = f2t(v.w);
            } else {
                *(uint4*)&Bs[bf][bR[i]][bC[i]] =
                    make_uint4(f2t(v.x), f2t(v.y), f2t(v.z), f2t(v.w));
            }
        }
    };

    float acc[MI][4][4] = {};
    int wm = wr * (MI * 16), wn = wc * 32;
    int KT = KSPL / BK, buf = 0;

    ldg(0); sts(0); __syncthreads();
    for (int kt = 0; kt < KT; kt++) {
        if (kt + 1 < KT) ldg(kt + 1);
        #pragma unroll
        for (int ks = 0; ks < BK / 8; ks++) {
            unsigned af[MI][4], bfr[4][2];
            #pragma unroll
            for (int mi = 0; mi < MI; mi++) {
                int m0 = wm + mi * 16 + g;
                af[mi][0] = As[buf][ks * 8 + t][m0];
                af[mi][1] = As[buf][ks * 8 + t][m0 + 8];
                af[mi][2] = As[buf][ks * 8 + t + 4][m0];
                af[mi][3] = As[buf][ks * 8 + t + 4][m0 + 8];
            }
            #pragma unroll
            for (int ni = 0; ni < 4; ni++) {
                int n0 = wn + ni * 8 + g;
                bfr[ni][0] = Bs[buf][ks * 8 + t][n0];
                bfr[ni][1] = Bs[buf][ks * 8 + t + 4][n0];
            }
            #pragma unroll
            for (int mi = 0; mi < MI; mi++)
                #pragma unroll
                for (int ni = 0; ni < 4; ni++)
                    mma8(acc[mi][ni], af[mi][0], af[mi][1], af[mi][2], af[mi][3],
                         bfr[ni][0], bfr[ni][1]);
        }
        if (kt + 1 < KT) { sts(buf ^ 1); __syncthreads(); buf ^= 1; }
    }

    long Cb = zb * sCb + zh * sCh + (long)sp * spC;
    int row0 = blockIdx.y * BM + wm;
    int ocol0 = (SRC3 ? blockIdx.x * BN : nb * BN) + wn;
    int bcolw = bcol0 + wn;
    #pragma unroll
    for (int mi = 0; mi < MI; mi++) {
        #pragma unroll
        for (int ni = 0; ni < 4; ni++) {
            int cl = ni * 8 + 2 * t;
            #pragma unroll
            for (int half = 0; half < 2; half++) {
                int r = row0 + mi * 16 + g + half * 8;
                float x = acc[mi][ni][half * 2], y = acc[mi][ni][half * 2 + 1];
                long idx = Cb + (long)r * ldc + ocol0 + cl;
                if (EPI == EPI_BIAS || EPI == EPI_BRELU) {
                    float2 bv = *(const float2*)(bias + bcolw + cl);
                    x += bv.x; y += bv.y;
                    if (EPI == EPI_BRELU) { x = fmaxf(x, 0.f); y = fmaxf(y, 0.f); }
                }
                if (EPI == EPI_SCL) { x *= 0.125f; y *= 0.125f; }
                st2v<CH>(C, idx, x, y);
            }
        }
    }
}

// ---------------- softmax: arg = S + 0.125*psum(half); fp16 probs out ----------
__global__ void softmax_k(const float* __restrict__ S, const __half* __restrict__ psum,
                          __half* __restrict__ P) {
    int t = threadIdx.x, warp = t >> 5, lane = t & 31;
    long row = (long)blockIdx.x * 8 + warp;
    const float4* rp = (const float4*)(S + row * 256);
    const __half2* pp = (const __half2*)(psum + row * 256);
    float4 a = rp[lane];
    float4 b = rp[lane + 32];
    float2 p0 = __half22float2(pp[2 * lane]);
    float2 p1 = __half22float2(pp[2 * lane + 1]);
    float2 p2 = __half22float2(pp[64 + 2 * lane]);
    float2 p3 = __half22float2(pp[64 + 2 * lane + 1]);
    a.x += 0.125f * p0.x; a.y += 0.125f * p0.y;
    a.z += 0.125f * p1.x; a.w += 0.125f * p1.y;
    b.x += 0.125f * p2.x; b.y += 0.125f * p2.y;
    b.z += 0.125f * p3.x; b.w += 0.125f * p3.y;
    float mx = fmaxf(fmaxf(fmaxf(a.x, a.y), fmaxf(a.z, a.w)),
                     fmaxf(fmaxf(b.x, b.y), fmaxf(b.z, b.w)));
    #pragma unroll
    for (int o = 16; o > 0; o >>= 1) mx = fmaxf(mx, __shfl_xor_sync(0xffffffffu, mx, o));
    a.x = __expf(a.x - mx); a.y = __expf(a.y - mx); a.z = __expf(a.z - mx); a.w = __expf(a.w - mx);
    b.x = __expf(b.x - mx); b.y = __expf(b.y - mx); b.z = __expf(b.z - mx); b.w = __expf(b.w - mx);
    float sm = a.x + a.y + a.z + a.w + b.x + b.y + b.z + b.w;
    #pragma unroll
    for (int o = 16; o > 0; o >>= 1) sm += __shfl_xor_sync(0xffffffffu, sm, o);
    float inv = 1.f / sm;
    __half2* hp = (__half2*)(P + row * 256);
    hp[2 * lane]          = __floats2half2_rn(a.x * inv, a.y * inv);
    hp[2 * lane + 1]      = __floats2half2_rn(a.z * inv, a.w * inv);
    hp[64 + 2 * lane]     = __floats2half2_rn(b.x * inv, b.y * inv);
    hp[64 + 2 * lane + 1] = __floats2half2_rn(b.z * inv, b.w * inv);
}

// ---------------- split-K reduce + bias + residual (+LN on residual) + stats ----
template<int PPART, int LNRES, int OFF>
__global__ void redres_k(const float* __restrict__ parts, const float* __restrict__ bias,
                         const float* __restrict__ R, float* __restrict__ X,
                         const float* __restrict__ lnw, const float* __restrict__ lnb) {
    __shared__ float shr[2][8];
    int gid = blockIdx.x * 256 + threadIdx.x;       // float4 index < 65536
    int bt = gid >> 14;
    float lnm = 0.f, lnri = 0.f;
    if (LNRES) {
        lnm = g_red[bt * 2] * (1.f / 65536.f);
        float var = g_red[bt * 2 + 1] * (1.f / 65536.f) - lnm * lnm;
        lnri = rsqrtf(var + 1e-5f);
    }
    const float4* pp = (const float4*)parts;
    float4 a = pp[gid];
    #pragma unroll
    for (int p = 1; p < PPART; p++) {
        float4 v = pp[gid + p * (TOT / 4)];
        a.x += v.x; a.y += v.y; a.z += v.z; a.w += v.w;
    }
    float4 bv = ((const float4*)bias)[gid & 63];
    float4 rv = ((const float4*)R)[gid];
    if (LNRES) {
        int p = gid & 16383;
        float4 wv = ((const float4*)lnw)[p];
        float4 lv = ((const float4*)lnb)[p];
        rv.x = (rv.x - lnm) * lnri * wv.x + lv.x;
        rv.y = (rv.y - lnm) * lnri * wv.y + lv.y;
        rv.z = (rv.z - lnm) * lnri * wv.z + lv.z;
        rv.w = (rv.w - lnm) * lnri * wv.w + lv.w;
    }
    a.x += bv.x + rv.x; a.y += bv.y + rv.y; a.z += bv.z + rv.z; a.w += bv.w + rv.w;
    ((float4*)X)[gid] = a;
    float s = a.x + a.y + a.z + a.w;
    float q = a.x * a.x + a.y * a.y + a.z * a.z + a.w * a.w;
    #pragma unroll
    for (int o = 16; o > 0; o >>= 1) {
        s += __shfl_xor_sync(0xffffffffu, s, o);
        q += __shfl_xor_sync(0xffffffffu, q, o);
    }
    int lane = threadIdx.x & 31, wp = threadIdx.x >> 5;
    if (lane == 0) { shr[0][wp] = s; shr[1][wp] = q; }
    __syncthreads();
    if (threadIdx.x == 0) {
        float ts = 0.f, tq = 0.f;
        #pragma unroll
        for (int i = 0; i < 8; i++) { ts += shr[0][i]; tq += shr[1][i]; }
        atomicAdd(&g_red[OFF + bt * 2], ts);
        atomicAdd(&g_red[OFF + bt * 2 + 1], tq);
    }
}

// ---------------- LayerNorm apply (final) ---------------------------------------
__global__ void ln_k(const float* __restrict__ X, const float* __restrict__ w,
                     const float* __restrict__ b, float* __restrict__ out) {
    int gid = blockIdx.x * blockDim.x + threadIdx.x;   // < 65536 float4s
    int bt = gid >> 14;
    float m   = g_red[8 + bt * 2] * (1.f / 65536.f);
    float var = g_red[8 + bt * 2 + 1] * (1.f / 65536.f) - m * m;
    float ri  = rsqrtf(var + 1e-5f);
    int p = gid & 16383;
    float4 x  = ((const float4*)X)[gid];
    float4 wv = ((const float4*)w)[p];
    float4 bv = ((const float4*)b)[p];
    float4 o;
    o.x = (x.x - m) * ri * wv.x + bv.x;
    o.y = (x.y - m) * ri * wv.y + bv.y;
    o.z = (x.z - m) * ri * wv.z + bv.z;
    o.w = (x.w - m) * ri * wv.w + bv.w;
    ((float4*)out)[gid] = o;
}

// ---------------- launch ----------------------------------------------------------
extern "C" void kernel_launch(void* const* d_in, const int* in_sizes, int n_in,
                              void* d_out, int out_size) {
    const float* feat = (const float*)d_in[0];
    const float* loc  = (const float*)d_in[1];
    const float* Kw   = (const float*)d_in[2];
    const float* Kb   = (const float*)d_in[3];
    const float* Qw   = (const float*)d_in[4];
    const float* Qb   = (const float*)d_in[5];
    const float* Vw   = (const float*)d_in[6];
    const float* Vb   = (const float*)d_in[7];
    const float* Fw   = (const float*)d_in[8];
    const float* Fb   = (const float*)d_in[9];
    const float* pe1w = (const float*)d_in[10];
    const float* pe1b = (const float*)d_in[11];
    const float* pe2w = (const float*)d_in[12];
    const float* pe2b = (const float*)d_in[13];
    const float* f1w  = (const float*)d_in[14];
    const float* f1b  = (const float*)d_in[15];
    const float* f2w  = (const float*)d_in[16];
    const float* f2b  = (const float*)d_in[17];
    const float* ln1w = (const float*)d_in[18];
    const float* ln1b = (const float*)d_in[19];
    const float* ln2w = (const float*)d_in[20];
    const float* ln2b = (const float*)d_in[21];
    float* out = (float*)d_out;

    __half *pQKV, *pPsum, *pPh, *pAvp, *pFfnh;
    float *pS, *pPart, *pRes1, *pRes2;
    cudaGetSymbolAddress((void**)&pQKV, g_QKVh);
    cudaGetSymbolAddress((void**)&pPsum, g_psumh);
    cudaGetSymbolAddress((void**)&pPh, g_Ph);
    cudaGetSymbolAddress((void**)&pAvp, g_avph);
    cudaGetSymbolAddress((void**)&pFfnh, g_ffnh);
    cudaGetSymbolAddress((void**)&pS, g_S);
    cudaGetSymbolAddress((void**)&pPart, g_part);
    cudaGetSymbolAddress((void**)&pRes1, g_res1);
    cudaGetSymbolAddress((void**)&pRes2, g_res2);

    // lazy one-time side-stream + events (resource init only; work identical per call)
    static cudaStream_t sPE = nullptr;
    static cudaEvent_t evFork = nullptr, evJoin = nullptr;
    if (sPE == nullptr) {
        cudaStreamCreateWithFlags(&sPE, cudaStreamNonBlocking);
        cudaEventCreateWithFlags(&evFork, cudaEventDisableTiming);
        cudaEventCreateWithFlags(&evJoin, cudaEventDisableTiming);
    }

    // ---- fork: PE branch on side stream ----
    cudaEventRecord(evFork, 0);
    cudaStreamWaitEvent(sPE, evFork, 0);
    prep_k<<<1, 128, 0, sPE>>>(pe2w, pe2b);
    pe_k<<<512, 256, 0, sPE>>>(loc, pe1w, pe1b);
    cudaEventRecord(evJoin, sPE);

    // ---- main branch: QKV -> scores (no psum dependency) ----
    gtc<64, 0, EPI_BIAS, 0, 12, 0, 0, 1, 0, 1><<<dim3(12, 16, 1), 128>>>(
        feat, nullptr, Qw, Kw, Vw, Qb, Kb, Vb, pQKV, nullptr, nullptr,
        256, 256, 256, 768, 0, 0, 0, 0, 0, 0, 0);

    // scores: per (b,h) K-rows · Q-rows^T * 0.125 -> S fp32  (BM=32, grid 512)
    gtc<32, 1, EPI_SCL, 0, 4, 1, 1, 0, 0, 0><<<dim3(4, 8, 16), 128>>>(
        pQKV + 256, nullptr, pQKV, nullptr, nullptr, nullptr, nullptr, nullptr,
        pS, nullptr, nullptr,
        64, 768, 768, 256, 196608, 64, 196608, 64, 262144, 65536, 0);

    // ---- join: softmax needs psum ----
    cudaStreamWaitEvent(0, evJoin, 0);
    softmax_k<<<512, 256>>>(pS, pPsum, pPh);

    // merged partials = attn(half) @ V(half), split-K 2 (BM=32, grid 256)
    gtc<32, 0, EPI_NONE, 0, 1, 1, 1, 1, 0, 0><<<dim3(2, 8, 16), 128>>>(
        pPh, nullptr, pQKV + 512, nullptr, nullptr, nullptr, nullptr, nullptr,
        pAvp, nullptr, nullptr,
        128, 256, 768, 256, 262144, 65536, 196608, 64, 65536, 64, TOT);

    // output projection: A = avp0+avp1 (half), split-K 2 -> part fp32
    gtc<64, 0, EPI_NONE, 1, 4, 1, 0, 0, 0, 0><<<dim3(8, 16, 1), 128>>>(
        pAvp, pAvp + TOT, Fw, nullptr, nullptr, nullptr, nullptr, nullptr,
        pPart, nullptr, nullptr,
        128, 256, 256, 256, 0, 0, 0, 0, 0, 0, TOT);

    // reduce + Fb + feat residual -> res1, LN1 stats -> red[0..7]
    redres_k<2, 0, 0><<<256, 256>>>(pPart, Fb, feat, pRes1, nullptr, nullptr);

    // FFN1: A = LN1(res1) on load; bias+relu -> ffnh (half)
    gtc<64, 0, EPI_BRELU, 0, 16, 0, 0, 1, 1, 0><<<dim3(16, 16, 1), 128>>>(
        pRes1, nullptr, f1w, nullptr, nullptr, f1b, nullptr, nullptr,
        pFfnh, ln1w, ln1b,
        256, 256, 1024, 1024, 0, 0, 0, 0, 0, 0, 0);

    // FFN2: A = ffnh (half), split-K 4 -> part fp32
    gtc<64, 0, EPI_NONE, 0, 4, 1, 0, 0, 0, 0><<<dim3(16, 16, 1), 128>>>(
        pFfnh, nullptr, f2w, nullptr, nullptr, nullptr, nullptr, nullptr,
        pPart, nullptr, nullptr,
        256, 1024, 256, 256, 0, 0, 0, 0, 0, 0, TOT);

    // reduce + f2b + LN1(res1) residual -> res2, LN2 stats -> red[8..15]
    redres_k<4, 1, 8><<<256, 256>>>(pPart, f2b, pRes1, pRes2, ln1w, ln1b);

    // final LN2 -> out
    ln_k<<<256, 256>>>(pRes2, ln2w, ln2b, out);
}